// round 1
// baseline (speedup 1.0000x reference)
#include <cuda_runtime.h>
#include <math.h>

// Problem shape (fixed by the dataset)
#define B_SZ 2
#define T_SZ 2048
#define E_SZ 1024
#define H_SZ 16
#define D_SZ 64
#define M_SZ (B_SZ * T_SZ)   // 4096 rows

// -------- scratch (static device arrays; no allocations allowed) --------
__device__ float g_q[M_SZ * E_SZ];
__device__ float g_k[M_SZ * E_SZ];
__device__ float g_v[M_SZ * E_SZ];
__device__ float g_ao[M_SZ * E_SZ];

// ======================= SGEMM + bias =======================
// C[M,N] = A[M,K] @ W[K,N] + bias[N]
// BM=BN=64, BK=16, 256 threads, 4x4 per thread. All dims multiples of tiles.
#define BM 64
#define BN 64
#define BK 16

__global__ __launch_bounds__(256) void sgemm_bias(
    const float* __restrict__ A, const float* __restrict__ W,
    const float* __restrict__ bias, float* __restrict__ C,
    int M, int N, int K)
{
    __shared__ float As[BK][BM + 1];  // [k][m], padded
    __shared__ float Ws[BK][BN];      // [k][n]

    const int tid = threadIdx.x;
    const int tx = tid & 15;       // 0..15  (cols)
    const int ty = tid >> 4;       // 0..15  (rows)
    const int row0 = blockIdx.y * BM;
    const int col0 = blockIdx.x * BN;

    float acc[4][4];
#pragma unroll
    for (int i = 0; i < 4; i++)
#pragma unroll
        for (int j = 0; j < 4; j++) acc[i][j] = 0.f;

    for (int k0 = 0; k0 < K; k0 += BK) {
        // A tile: 64x16. Each thread: one float4.  m=tid/4, kk=(tid%4)*4
        {
            int m  = tid >> 2;
            int kk = (tid & 3) * 4;
            float4 a4 = *reinterpret_cast<const float4*>(&A[(size_t)(row0 + m) * K + k0 + kk]);
            As[kk + 0][m] = a4.x;
            As[kk + 1][m] = a4.y;
            As[kk + 2][m] = a4.z;
            As[kk + 3][m] = a4.w;
        }
        // W tile: 16x64. Each thread: one float4. kk=tid/16, n=(tid%16)*4
        {
            int kk = tid >> 4;
            int n  = (tid & 15) * 4;
            float4 w4 = *reinterpret_cast<const float4*>(&W[(size_t)(k0 + kk) * N + col0 + n]);
            *reinterpret_cast<float4*>(&Ws[kk][n]) = w4;
        }
        __syncthreads();

#pragma unroll
        for (int k = 0; k < BK; k++) {
            float a[4];
#pragma unroll
            for (int i = 0; i < 4; i++) a[i] = As[k][ty * 4 + i];
            float4 w4 = *reinterpret_cast<const float4*>(&Ws[k][tx * 4]);
            float w[4] = {w4.x, w4.y, w4.z, w4.w};
#pragma unroll
            for (int i = 0; i < 4; i++)
#pragma unroll
                for (int j = 0; j < 4; j++) acc[i][j] = fmaf(a[i], w[j], acc[i][j]);
        }
        __syncthreads();
    }

#pragma unroll
    for (int i = 0; i < 4; i++) {
        int r = row0 + ty * 4 + i;
        int c = col0 + tx * 4;
        float4 bv = *reinterpret_cast<const float4*>(&bias[c]);
        float4 res;
        res.x = acc[i][0] + bv.x;
        res.y = acc[i][1] + bv.y;
        res.z = acc[i][2] + bv.z;
        res.w = acc[i][3] + bv.w;
        *reinterpret_cast<float4*>(&C[(size_t)r * N + c]) = res;
    }
}

// ======================= Flash attention (fp32, causal) =======================
// softmax((QK^T + mask*(-1e9)) / 32): masked entries go to -3.1e7 => exp == 0
// in fp32, so causal flash with scale 1/32 is exact.
// Block: 256 threads, computes a 64(query) x 64(headdim) output tile.
// Grid: (T/64, H, B).

#define FBR 64
#define FBC 64
#define QS_STRIDE 68
#define KT_STRIDE 68
#define VS_STRIDE 68
#define PS_STRIDE 64

#define FLASH_SMEM_FLOATS (FBR*QS_STRIDE + D_SZ*KT_STRIDE + FBC*VS_STRIDE + FBR*PS_STRIDE)
#define FLASH_SMEM_BYTES  (FLASH_SMEM_FLOATS * 4)

__global__ __launch_bounds__(256) void flash_attn_kernel(
    const float* __restrict__ Qg, const float* __restrict__ Kg,
    const float* __restrict__ Vg, float* __restrict__ Og)
{
    extern __shared__ float sm[];
    float* Qs = sm;                          // [r][d]  stride 68
    float* Kt = Qs + FBR * QS_STRIDE;        // [d][c]  stride 68 (transposed K)
    float* Vs = Kt + D_SZ * KT_STRIDE;       // [c][d]  stride 68
    float* Ps = Vs + FBC * VS_STRIDE;        // [r][c]  stride 64

    const int iq = blockIdx.x;
    const int h  = blockIdx.y;
    const int b  = blockIdx.z;
    const int tid = threadIdx.x;
    const int tx = tid & 15;
    const int ty = tid >> 4;
    const int r0 = iq * FBR;

    const size_t base = (size_t)b * T_SZ * E_SZ + (size_t)h * D_SZ;

    // ---- load Q tile: thread loads row r=tid/4, 4 float4 chunks ----
    {
        int r  = tid >> 2;
        int d0 = (tid & 3) * 4;
        const float* src = Qg + base + (size_t)(r0 + r) * E_SZ;
#pragma unroll
        for (int w = 0; w < 4; w++) {
            float4 v = *reinterpret_cast<const float4*>(src + d0 + w * 16);
            *reinterpret_cast<float4*>(&Qs[r * QS_STRIDE + d0 + w * 16]) = v;
        }
    }

    float m_i[4], l_i[4], o[4][4];
#pragma unroll
    for (int i = 0; i < 4; i++) {
        m_i[i] = -INFINITY;
        l_i[i] = 0.f;
#pragma unroll
        for (int j = 0; j < 4; j++) o[i][j] = 0.f;
    }

    const float scale = 0.03125f;  // 1/sqrt(1024)

    for (int jc = 0; jc <= iq; jc++) {
        const int c0 = jc * FBC;
        __syncthreads();  // previous-iter readers done; (iter 0: Qs visibility comes from next sync)

        // ---- load K tile transposed + V tile ----
        {
            int c  = tid >> 2;
            int d0 = (tid & 3) * 4;
            const float* ksrc = Kg + base + (size_t)(c0 + c) * E_SZ;
            const float* vsrc = Vg + base + (size_t)(c0 + c) * E_SZ;
#pragma unroll
            for (int w = 0; w < 4; w++) {
                int d = d0 + w * 16;
                float4 kv = *reinterpret_cast<const float4*>(ksrc + d);
                Kt[(d + 0) * KT_STRIDE + c] = kv.x;
                Kt[(d + 1) * KT_STRIDE + c] = kv.y;
                Kt[(d + 2) * KT_STRIDE + c] = kv.z;
                Kt[(d + 3) * KT_STRIDE + c] = kv.w;
                float4 vv = *reinterpret_cast<const float4*>(vsrc + d);
                *reinterpret_cast<float4*>(&Vs[c * VS_STRIDE + d]) = vv;
            }
        }
        __syncthreads();

        // ---- S = (Q K^T) * scale, thread owns 4x4 ----
        float s[4][4];
#pragma unroll
        for (int i = 0; i < 4; i++)
#pragma unroll
            for (int j = 0; j < 4; j++) s[i][j] = 0.f;

#pragma unroll 16
        for (int d = 0; d < D_SZ; d++) {
            float a[4];
#pragma unroll
            for (int i = 0; i < 4; i++) a[i] = Qs[(ty * 4 + i) * QS_STRIDE + d];
            float4 k4 = *reinterpret_cast<const float4*>(&Kt[d * KT_STRIDE + tx * 4]);
            float kb[4] = {k4.x, k4.y, k4.z, k4.w};
#pragma unroll
            for (int i = 0; i < 4; i++)
#pragma unroll
                for (int j = 0; j < 4; j++) s[i][j] = fmaf(a[i], kb[j], s[i][j]);
        }

        if (jc == iq) {
            // diagonal tile: causal mask (col > row => -inf)
#pragma unroll
            for (int i = 0; i < 4; i++) {
                int r = r0 + ty * 4 + i;
#pragma unroll
                for (int j = 0; j < 4; j++) {
                    int c = c0 + tx * 4 + j;
                    s[i][j] = (c > r) ? -INFINITY : s[i][j] * scale;
                }
            }
        } else {
#pragma unroll
            for (int i = 0; i < 4; i++)
#pragma unroll
                for (int j = 0; j < 4; j++) s[i][j] *= scale;
        }

        // ---- online softmax update (reduce across 16 tx lanes, xor<=8 stays in half) ----
#pragma unroll
        for (int i = 0; i < 4; i++) {
            float mx = fmaxf(fmaxf(s[i][0], s[i][1]), fmaxf(s[i][2], s[i][3]));
#pragma unroll
            for (int msk = 8; msk >= 1; msk >>= 1)
                mx = fmaxf(mx, __shfl_xor_sync(0xffffffffu, mx, msk));
            float mnew = fmaxf(m_i[i], mx);
            float alpha = __expf(m_i[i] - mnew);  // exp(-inf)=0 on first tile
            float sum = 0.f;
#pragma unroll
            for (int j = 0; j < 4; j++) {
                float p = __expf(s[i][j] - mnew);
                s[i][j] = p;
                sum += p;
            }
#pragma unroll
            for (int msk = 8; msk >= 1; msk >>= 1)
                sum += __shfl_xor_sync(0xffffffffu, sum, msk);
            l_i[i] = l_i[i] * alpha + sum;
            m_i[i] = mnew;
#pragma unroll
            for (int j = 0; j < 4; j++) o[i][j] *= alpha;
        }

        // ---- write P tile ----
#pragma unroll
        for (int i = 0; i < 4; i++) {
            float4 p4 = {s[i][0], s[i][1], s[i][2], s[i][3]};
            *reinterpret_cast<float4*>(&Ps[(ty * 4 + i) * PS_STRIDE + tx * 4]) = p4;
        }
        __syncthreads();

        // ---- O += P @ V ----
#pragma unroll 8
        for (int c = 0; c < FBC; c++) {
            float p[4];
#pragma unroll
            for (int i = 0; i < 4; i++) p[i] = Ps[(ty * 4 + i) * PS_STRIDE + c];
            float4 v4 = *reinterpret_cast<const float4*>(&Vs[c * VS_STRIDE + tx * 4]);
            float vb[4] = {v4.x, v4.y, v4.z, v4.w};
#pragma unroll
            for (int i = 0; i < 4; i++)
#pragma unroll
                for (int j = 0; j < 4; j++) o[i][j] = fmaf(p[i], vb[j], o[i][j]);
        }
    }

    // ---- epilogue: normalize + store to [B,T,H,D] scratch ----
#pragma unroll
    for (int i = 0; i < 4; i++) {
        float inv = 1.f / l_i[i];
        int t = r0 + ty * 4 + i;
        float4 res = {o[i][0] * inv, o[i][1] * inv, o[i][2] * inv, o[i][3] * inv};
        *reinterpret_cast<float4*>(Og + base + (size_t)t * E_SZ + tx * 4) = res;
    }
}

// ======================= launch =======================
extern "C" void kernel_launch(void* const* d_in, const int* in_sizes, int n_in,
                              void* d_out, int out_size)
{
    const float* x  = (const float*)d_in[0];
    const float* Wq = (const float*)d_in[1];
    const float* bq = (const float*)d_in[2];
    const float* Wk = (const float*)d_in[3];
    const float* bk = (const float*)d_in[4];
    const float* Wv = (const float*)d_in[5];
    const float* bv = (const float*)d_in[6];
    const float* Wo = (const float*)d_in[7];
    const float* bo = (const float*)d_in[8];
    float* out = (float*)d_out;

    float *gq, *gk, *gv, *gao;
    cudaGetSymbolAddress((void**)&gq,  g_q);
    cudaGetSymbolAddress((void**)&gk,  g_k);
    cudaGetSymbolAddress((void**)&gv,  g_v);
    cudaGetSymbolAddress((void**)&gao, g_ao);

    dim3 ggrid(E_SZ / BN, M_SZ / BM);  // (16, 64)

    sgemm_bias<<<ggrid, 256>>>(x, Wq, bq, gq, M_SZ, E_SZ, E_SZ);
    sgemm_bias<<<ggrid, 256>>>(x, Wk, bk, gk, M_SZ, E_SZ, E_SZ);
    sgemm_bias<<<ggrid, 256>>>(x, Wv, bv, gv, M_SZ, E_SZ, E_SZ);

    cudaFuncSetAttribute(flash_attn_kernel,
                         cudaFuncAttributeMaxDynamicSharedMemorySize, FLASH_SMEM_BYTES);
    flash_attn_kernel<<<dim3(T_SZ / FBR, H_SZ, B_SZ), 256, FLASH_SMEM_BYTES>>>(gq, gk, gv, gao);

    sgemm_bias<<<ggrid, 256>>>(gao, Wo, bo, out, M_SZ, E_SZ, E_SZ);
}

// round 3
// speedup vs baseline: 1.7285x; 1.7285x over previous
#include <cuda_runtime.h>
#include <cuda_bf16.h>
#include <math.h>
#include <stdint.h>

// Problem shape (fixed by the dataset)
#define B_SZ 2
#define T_SZ 2048
#define E_SZ 1024
#define H_SZ 16
#define D_SZ 64
#define M_SZ (B_SZ * T_SZ)   // 4096 rows

// ---------------- scratch (static device arrays; no allocation) ----------------
__device__ __align__(256) float g_q[M_SZ * E_SZ];
__device__ __align__(256) float g_k[M_SZ * E_SZ];
__device__ __align__(256) float g_v[M_SZ * E_SZ];
__device__ __align__(256) float g_ao[M_SZ * E_SZ];

__device__ __align__(256) __nv_bfloat16 g_x_hi[M_SZ * E_SZ];
__device__ __align__(256) __nv_bfloat16 g_x_lo[M_SZ * E_SZ];
__device__ __align__(256) __nv_bfloat16 g_ao_hi[M_SZ * E_SZ];
__device__ __align__(256) __nv_bfloat16 g_ao_lo[M_SZ * E_SZ];

__device__ __align__(256) __nv_bfloat16 g_wq_hi[E_SZ * E_SZ];
__device__ __align__(256) __nv_bfloat16 g_wq_lo[E_SZ * E_SZ];
__device__ __align__(256) __nv_bfloat16 g_wk_hi[E_SZ * E_SZ];
__device__ __align__(256) __nv_bfloat16 g_wk_lo[E_SZ * E_SZ];
__device__ __align__(256) __nv_bfloat16 g_wv_hi[E_SZ * E_SZ];
__device__ __align__(256) __nv_bfloat16 g_wv_lo[E_SZ * E_SZ];
__device__ __align__(256) __nv_bfloat16 g_wo_hi[E_SZ * E_SZ];
__device__ __align__(256) __nv_bfloat16 g_wo_lo[E_SZ * E_SZ];

// ================= helpers =================
__device__ __forceinline__ uint32_t smem_u32(const void* p) {
    return (uint32_t)__cvta_generic_to_shared(p);
}

__device__ __forceinline__ void cp_async16(uint32_t dst, const void* src) {
    asm volatile("cp.async.cg.shared.global [%0], [%1], 16;" :: "r"(dst), "l"(src));
}

__device__ __forceinline__ void ldsm_x4(uint32_t addr, uint32_t& r0, uint32_t& r1,
                                        uint32_t& r2, uint32_t& r3) {
    asm volatile("ldmatrix.sync.aligned.m8n8.x4.shared.b16 {%0,%1,%2,%3}, [%4];"
                 : "=r"(r0), "=r"(r1), "=r"(r2), "=r"(r3) : "r"(addr));
}

__device__ __forceinline__ void mma_bf16(float* d, const uint32_t* a, const uint32_t* b) {
    asm volatile(
        "mma.sync.aligned.m16n8k16.row.col.f32.bf16.bf16.f32 "
        "{%0,%1,%2,%3}, {%4,%5,%6,%7}, {%8,%9}, {%0,%1,%2,%3};"
        : "+f"(d[0]), "+f"(d[1]), "+f"(d[2]), "+f"(d[3])
        : "r"(a[0]), "r"(a[1]), "r"(a[2]), "r"(a[3]), "r"(b[0]), "r"(b[1]));
}

// swizzled smem offset for 64-byte rows (BK=32 bf16), 16B chunks permuted by (row>>1)&3
__device__ __forceinline__ uint32_t swz(int r, int chunk) {
    return (uint32_t)(r * 64 + ((chunk ^ ((r >> 1) & 3)) << 4));
}

// ================= conversion kernels =================
__global__ __launch_bounds__(256) void convert_split(
    const float4* __restrict__ in, __nv_bfloat162* __restrict__ hi,
    __nv_bfloat162* __restrict__ lo, int n4)
{
    int i = blockIdx.x * 256 + threadIdx.x;
    if (i >= n4) return;
    float4 v = in[i];
    __nv_bfloat16 hx = __float2bfloat16(v.x);
    __nv_bfloat16 hy = __float2bfloat16(v.y);
    __nv_bfloat16 hz = __float2bfloat16(v.z);
    __nv_bfloat16 hw = __float2bfloat16(v.w);
    __nv_bfloat16 lx = __float2bfloat16(v.x - __bfloat162float(hx));
    __nv_bfloat16 ly = __float2bfloat16(v.y - __bfloat162float(hy));
    __nv_bfloat16 lz = __float2bfloat16(v.z - __bfloat162float(hz));
    __nv_bfloat16 lw = __float2bfloat16(v.w - __bfloat162float(hw));
    hi[2 * i + 0] = __halves2bfloat162(hx, hy);
    hi[2 * i + 1] = __halves2bfloat162(hz, hw);
    lo[2 * i + 0] = __halves2bfloat162(lx, ly);
    lo[2 * i + 1] = __halves2bfloat162(lz, lw);
}

// W [K,N] fp32 -> Wt [N,K] bf16 hi/lo  (B operand K-major, i.e. col-major for mma)
__global__ __launch_bounds__(256) void transpose_split(
    const float* __restrict__ W, __nv_bfloat16* __restrict__ Th,
    __nv_bfloat16* __restrict__ Tl)
{
    __shared__ float t[32][33];
    int n0 = blockIdx.x * 32, k0 = blockIdx.y * 32;
    int tx = threadIdx.x & 31;
    int ty = threadIdx.x >> 5;
#pragma unroll
    for (int i = 0; i < 4; i++)
        t[ty + i * 8][tx] = W[(size_t)(k0 + ty + i * 8) * E_SZ + n0 + tx];
    __syncthreads();
#pragma unroll
    for (int i = 0; i < 4; i++) {
        float v = t[tx][ty + i * 8];
        int n = n0 + ty + i * 8, k = k0 + tx;
        __nv_bfloat16 h = __float2bfloat16(v);
        Th[(size_t)n * E_SZ + k] = h;
        Tl[(size_t)n * E_SZ + k] = __float2bfloat16(v - __bfloat162float(h));
    }
}

// ================= HMMA GEMM (bf16 split, fp32 accum) =================
// C[128x128] per CTA, 8 warps (2x4), warp tile 64x32, BK=32, double buffered.
// SMEM stage: A_hi(8K) A_lo(8K) B_hi(8K) B_lo(8K) = 32KB; 2 stages = 64KB.
#define HT 8192
#define HSTAGE 32768
#define H_SMEM 65536
#define NSTAGES 32   // K=1024 / 32

__device__ __forceinline__ void h_load_tile(uint32_t dst, const __nv_bfloat16* src,
                                            int row0, int k0, int tid) {
#pragma unroll
    for (int i = 0; i < 2; i++) {
        int idx = tid + (i << 8);        // 0..511
        int r = idx >> 2, c = idx & 3;
        cp_async16(dst + swz(r, c),
                   (const void*)(src + (size_t)(row0 + r) * E_SZ + k0 + (c << 3)));
    }
}

__global__ __launch_bounds__(256) void gemm_hmma(
    const __nv_bfloat16* __restrict__ Ah, const __nv_bfloat16* __restrict__ Al,
    const __nv_bfloat16* __restrict__ Bh, const __nv_bfloat16* __restrict__ Bl,
    const float* __restrict__ bias, float* __restrict__ C)
{
    extern __shared__ char smem[];
    const uint32_t sb = smem_u32(smem);
    const int tid = threadIdx.x;
    const int wid = tid >> 5, lane = tid & 31;
    const int wm = wid >> 2, wn = wid & 3;      // 2 x 4 warp grid
    const int n0 = blockIdx.x * 128, m0 = blockIdx.y * 128;
    const int g = lane >> 3, l8 = lane & 7;

    float acc[4][4][4];   // [m-tile][n8-tile][regs]
#pragma unroll
    for (int mt = 0; mt < 4; mt++)
#pragma unroll
        for (int nt = 0; nt < 4; nt++)
#pragma unroll
            for (int r = 0; r < 4; r++) acc[mt][nt][r] = 0.f;

    // prologue: stages 0 and 1
    h_load_tile(sb + 0 * HT, Ah, m0, 0, tid);
    h_load_tile(sb + 1 * HT, Al, m0, 0, tid);
    h_load_tile(sb + 2 * HT, Bh, n0, 0, tid);
    h_load_tile(sb + 3 * HT, Bl, n0, 0, tid);
    asm volatile("cp.async.commit_group;" ::: "memory");
    h_load_tile(sb + HSTAGE + 0 * HT, Ah, m0, 32, tid);
    h_load_tile(sb + HSTAGE + 1 * HT, Al, m0, 32, tid);
    h_load_tile(sb + HSTAGE + 2 * HT, Bh, n0, 32, tid);
    h_load_tile(sb + HSTAGE + 3 * HT, Bl, n0, 32, tid);
    asm volatile("cp.async.commit_group;" ::: "memory");

    for (int s = 0; s < NSTAGES; s++) {
        if (s + 2 < NSTAGES)
            asm volatile("cp.async.wait_group 1;" ::: "memory");
        else
            asm volatile("cp.async.wait_group 0;" ::: "memory");
        __syncthreads();

        const uint32_t st = sb + (uint32_t)(s & 1) * HSTAGE;
        const uint32_t sAh = st + 0 * HT, sAl = st + 1 * HT;
        const uint32_t sBh = st + 2 * HT, sBl = st + 3 * HT;

#pragma unroll
        for (int k16 = 0; k16 < 2; k16++) {
            const int cb = k16 * 2;
            uint32_t ah[4][4], al[4][4], bh[2][4], bl[2][4];
            // A frags: 4 m16 tiles
#pragma unroll
            for (int mt = 0; mt < 4; mt++) {
                int r = wm * 64 + mt * 16 + (g & 1) * 8 + l8;
                int c = cb + (g >> 1);
                ldsm_x4(sAh + swz(r, c), ah[mt][0], ah[mt][1], ah[mt][2], ah[mt][3]);
                ldsm_x4(sAl + swz(r, c), al[mt][0], al[mt][1], al[mt][2], al[mt][3]);
            }
            // B frags: 2 n16 groups
#pragma unroll
            for (int bt = 0; bt < 2; bt++) {
                int r = wn * 32 + bt * 16 + (g >> 1) * 8 + l8;
                int c = cb + (g & 1);
                ldsm_x4(sBh + swz(r, c), bh[bt][0], bh[bt][1], bh[bt][2], bh[bt][3]);
                ldsm_x4(sBl + swz(r, c), bl[bt][0], bl[bt][1], bl[bt][2], bl[bt][3]);
            }
#pragma unroll
            for (int mt = 0; mt < 4; mt++)
#pragma unroll
                for (int nt = 0; nt < 4; nt++) {
                    const int bg = nt >> 1, hs = (nt & 1) * 2;
                    uint32_t bhh[2] = {bh[bg][hs], bh[bg][hs + 1]};
                    uint32_t bll[2] = {bl[bg][hs], bl[bg][hs + 1]};
                    mma_bf16(acc[mt][nt], ah[mt], bhh);
                    mma_bf16(acc[mt][nt], al[mt], bhh);
                    mma_bf16(acc[mt][nt], ah[mt], bll);
                }
        }
        __syncthreads();

        if (s + 2 < NSTAGES) {
            const uint32_t dt = sb + (uint32_t)(s & 1) * HSTAGE;
            const int k0 = (s + 2) * 32;
            h_load_tile(dt + 0 * HT, Ah, m0, k0, tid);
            h_load_tile(dt + 1 * HT, Al, m0, k0, tid);
            h_load_tile(dt + 2 * HT, Bh, n0, k0, tid);
            h_load_tile(dt + 3 * HT, Bl, n0, k0, tid);
            asm volatile("cp.async.commit_group;" ::: "memory");
        }
    }

    // epilogue: bias + store
    const int qr = lane >> 2, qc = (lane & 3) * 2;
#pragma unroll
    for (int mt = 0; mt < 4; mt++) {
#pragma unroll
        for (int nt = 0; nt < 4; nt++) {
            int col = n0 + wn * 32 + nt * 8 + qc;
            float2 bv = *(const float2*)(bias + col);
            int row_a = m0 + wm * 64 + mt * 16 + qr;
            float2 o0 = {acc[mt][nt][0] + bv.x, acc[mt][nt][1] + bv.y};
            float2 o1 = {acc[mt][nt][2] + bv.x, acc[mt][nt][3] + bv.y};
            *(float2*)(C + (size_t)row_a * E_SZ + col) = o0;
            *(float2*)(C + (size_t)(row_a + 8) * E_SZ + col) = o1;
        }
    }
}

// ======================= Flash attention (fp32, causal) =======================
#define FBR 64
#define FBC 64
#define QS_STRIDE 68
#define KT_STRIDE 68
#define VS_STRIDE 68
#define PS_STRIDE 64

#define FLASH_SMEM_FLOATS (FBR*QS_STRIDE + D_SZ*KT_STRIDE + FBC*VS_STRIDE + FBR*PS_STRIDE)
#define FLASH_SMEM_BYTES  (FLASH_SMEM_FLOATS * 4)

__global__ __launch_bounds__(256) void flash_attn_kernel(
    const float* __restrict__ Qg, const float* __restrict__ Kg,
    const float* __restrict__ Vg, float* __restrict__ Og)
{
    extern __shared__ float sm[];
    float* Qs = sm;
    float* Kt = Qs + FBR * QS_STRIDE;
    float* Vs = Kt + D_SZ * KT_STRIDE;
    float* Ps = Vs + FBC * VS_STRIDE;

    const int iq = blockIdx.x;
    const int h  = blockIdx.y;
    const int b  = blockIdx.z;
    const int tid = threadIdx.x;
    const int tx = tid & 15;
    const int ty = tid >> 4;
    const int r0 = iq * FBR;

    const size_t base = (size_t)b * T_SZ * E_SZ + (size_t)h * D_SZ;

    {
        int r  = tid >> 2;
        int d0 = (tid & 3) * 4;
        const float* src = Qg + base + (size_t)(r0 + r) * E_SZ;
#pragma unroll
        for (int w = 0; w < 4; w++) {
            float4 v = *reinterpret_cast<const float4*>(src + d0 + w * 16);
            *reinterpret_cast<float4*>(&Qs[r * QS_STRIDE + d0 + w * 16]) = v;
        }
    }

    float m_i[4], l_i[4], o[4][4];
#pragma unroll
    for (int i = 0; i < 4; i++) {
        m_i[i] = -INFINITY;
        l_i[i] = 0.f;
#pragma unroll
        for (int j = 0; j < 4; j++) o[i][j] = 0.f;
    }

    const float scale = 0.03125f;

    for (int jc = 0; jc <= iq; jc++) {
        const int c0 = jc * FBC;
        __syncthreads();

        {
            int c  = tid >> 2;
            int d0 = (tid & 3) * 4;
            const float* ksrc = Kg + base + (size_t)(c0 + c) * E_SZ;
            const float* vsrc = Vg + base + (size_t)(c0 + c) * E_SZ;
#pragma unroll
            for (int w = 0; w < 4; w++) {
                int d = d0 + w * 16;
                float4 kv = *reinterpret_cast<const float4*>(ksrc + d);
                Kt[(d + 0) * KT_STRIDE + c] = kv.x;
                Kt[(d + 1) * KT_STRIDE + c] = kv.y;
                Kt[(d + 2) * KT_STRIDE + c] = kv.z;
                Kt[(d + 3) * KT_STRIDE + c] = kv.w;
                float4 vv = *reinterpret_cast<const float4*>(vsrc + d);
                *reinterpret_cast<float4*>(&Vs[c * VS_STRIDE + d]) = vv;
            }
        }
        __syncthreads();

        float s[4][4];
#pragma unroll
        for (int i = 0; i < 4; i++)
#pragma unroll
            for (int j = 0; j < 4; j++) s[i][j] = 0.f;

#pragma unroll 16
        for (int d = 0; d < D_SZ; d++) {
            float a[4];
#pragma unroll
            for (int i = 0; i < 4; i++) a[i] = Qs[(ty * 4 + i) * QS_STRIDE + d];
            float4 k4 = *reinterpret_cast<const float4*>(&Kt[d * KT_STRIDE + tx * 4]);
            float kb[4] = {k4.x, k4.y, k4.z, k4.w};
#pragma unroll
            for (int i = 0; i < 4; i++)
#pragma unroll
                for (int j = 0; j < 4; j++) s[i][j] = fmaf(a[i], kb[j], s[i][j]);
        }

        if (jc == iq) {
#pragma unroll
            for (int i = 0; i < 4; i++) {
                int r = r0 + ty * 4 + i;
#pragma unroll
                for (int j = 0; j < 4; j++) {
                    int c = c0 + tx * 4 + j;
                    s[i][j] = (c > r) ? -INFINITY : s[i][j] * scale;
                }
            }
        } else {
#pragma unroll
            for (int i = 0; i < 4; i++)
#pragma unroll
                for (int j = 0; j < 4; j++) s[i][j] *= scale;
        }

#pragma unroll
        for (int i = 0; i < 4; i++) {
            float mx = fmaxf(fmaxf(s[i][0], s[i][1]), fmaxf(s[i][2], s[i][3]));
#pragma unroll
            for (int msk = 8; msk >= 1; msk >>= 1)
                mx = fmaxf(mx, __shfl_xor_sync(0xffffffffu, mx, msk));
            float mnew = fmaxf(m_i[i], mx);
            float alpha = __expf(m_i[i] - mnew);
            float sum = 0.f;
#pragma unroll
            for (int j = 0; j < 4; j++) {
                float p = __expf(s[i][j] - mnew);
                s[i][j] = p;
                sum += p;
            }
#pragma unroll
            for (int msk = 8; msk >= 1; msk >>= 1)
                sum += __shfl_xor_sync(0xffffffffu, sum, msk);
            l_i[i] = l_i[i] * alpha + sum;
            m_i[i] = mnew;
#pragma unroll
            for (int j = 0; j < 4; j++) o[i][j] *= alpha;
        }

#pragma unroll
        for (int i = 0; i < 4; i++) {
            float4 p4 = {s[i][0], s[i][1], s[i][2], s[i][3]};
            *reinterpret_cast<float4*>(&Ps[(ty * 4 + i) * PS_STRIDE + tx * 4]) = p4;
        }
        __syncthreads();

#pragma unroll 8
        for (int c = 0; c < FBC; c++) {
            float p[4];
#pragma unroll
            for (int i = 0; i < 4; i++) p[i] = Ps[(ty * 4 + i) * PS_STRIDE + c];
            float4 v4 = *reinterpret_cast<const float4*>(&Vs[c * VS_STRIDE + tx * 4]);
            float vb[4] = {v4.x, v4.y, v4.z, v4.w};
#pragma unroll
            for (int i = 0; i < 4; i++)
#pragma unroll
                for (int j = 0; j < 4; j++) o[i][j] = fmaf(p[i], vb[j], o[i][j]);
        }
    }

#pragma unroll
    for (int i = 0; i < 4; i++) {
        float inv = 1.f / l_i[i];
        int t = r0 + ty * 4 + i;
        float4 res = {o[i][0] * inv, o[i][1] * inv, o[i][2] * inv, o[i][3] * inv};
        *reinterpret_cast<float4*>(Og + base + (size_t)t * E_SZ + tx * 4) = res;
    }
}

// ======================= launch =======================
extern "C" void kernel_launch(void* const* d_in, const int* in_sizes, int n_in,
                              void* d_out, int out_size)
{
    const float* x  = (const float*)d_in[0];
    const float* Wq = (const float*)d_in[1];
    const float* bq = (const float*)d_in[2];
    const float* Wk = (const float*)d_in[3];
    const float* bk = (const float*)d_in[4];
    const float* Wv = (const float*)d_in[5];
    const float* bv = (const float*)d_in[6];
    const float* Wo = (const float*)d_in[7];
    const float* bo = (const float*)d_in[8];
    float* out = (float*)d_out;

    float *gq, *gk, *gv, *gao;
    cudaGetSymbolAddress((void**)&gq,  g_q);
    cudaGetSymbolAddress((void**)&gk,  g_k);
    cudaGetSymbolAddress((void**)&gv,  g_v);
    cudaGetSymbolAddress((void**)&gao, g_ao);

    __nv_bfloat16 *xh, *xl, *aoh, *aol;
    cudaGetSymbolAddress((void**)&xh,  g_x_hi);
    cudaGetSymbolAddress((void**)&xl,  g_x_lo);
    cudaGetSymbolAddress((void**)&aoh, g_ao_hi);
    cudaGetSymbolAddress((void**)&aol, g_ao_lo);

    __nv_bfloat16 *wqh, *wql, *wkh, *wkl, *wvh, *wvl, *woh, *wol;
    cudaGetSymbolAddress((void**)&wqh, g_wq_hi);
    cudaGetSymbolAddress((void**)&wql, g_wq_lo);
    cudaGetSymbolAddress((void**)&wkh, g_wk_hi);
    cudaGetSymbolAddress((void**)&wkl, g_wk_lo);
    cudaGetSymbolAddress((void**)&wvh, g_wv_hi);
    cudaGetSymbolAddress((void**)&wvl, g_wv_lo);
    cudaGetSymbolAddress((void**)&woh, g_wo_hi);
    cudaGetSymbolAddress((void**)&wol, g_wo_lo);

    cudaFuncSetAttribute(gemm_hmma, cudaFuncAttributeMaxDynamicSharedMemorySize, H_SMEM);
    cudaFuncSetAttribute(flash_attn_kernel, cudaFuncAttributeMaxDynamicSharedMemorySize,
                         FLASH_SMEM_BYTES);

    const int n4 = (M_SZ * E_SZ) / 4;

    // 1) split x
    convert_split<<<(n4 + 255) / 256, 256>>>((const float4*)x,
        (__nv_bfloat162*)xh, (__nv_bfloat162*)xl, n4);

    // 2) transpose+split weights: Wt[N,K]
    dim3 tgrid(E_SZ / 32, E_SZ / 32);
    transpose_split<<<tgrid, 256>>>(Wq, wqh, wql);
    transpose_split<<<tgrid, 256>>>(Wk, wkh, wkl);
    transpose_split<<<tgrid, 256>>>(Wv, wvh, wvl);
    transpose_split<<<tgrid, 256>>>(Wo, woh, wol);

    // 3) Q/K/V projections on HMMA
    dim3 ggrid(E_SZ / 128, M_SZ / 128);   // (8, 32)
    gemm_hmma<<<ggrid, 256, H_SMEM>>>(xh, xl, wqh, wql, bq, gq);
    gemm_hmma<<<ggrid, 256, H_SMEM>>>(xh, xl, wkh, wkl, bk, gk);
    gemm_hmma<<<ggrid, 256, H_SMEM>>>(xh, xl, wvh, wvl, bv, gv);

    // 4) attention
    flash_attn_kernel<<<dim3(T_SZ / FBR, H_SZ, B_SZ), 256, FLASH_SMEM_BYTES>>>(gq, gk, gv, gao);

    // 5) split attention output, then O projection
    convert_split<<<(n4 + 255) / 256, 256>>>((const float4*)gao,
        (__nv_bfloat162*)aoh, (__nv_bfloat162*)aol, n4);
    gemm_hmma<<<ggrid, 256, H_SMEM>>>(aoh, aol, woh, wol, bo, out);
}

// round 4
// speedup vs baseline: 3.1244x; 1.8076x over previous
#include <cuda_runtime.h>
#include <cuda_bf16.h>
#include <math.h>
#include <stdint.h>

// Problem shape (fixed by the dataset)
#define B_SZ 2
#define T_SZ 2048
#define E_SZ 1024
#define H_SZ 16
#define D_SZ 64
#define M_SZ (B_SZ * T_SZ)   // 4096 rows

// ---------------- scratch (static device arrays; no allocation) ----------------
__device__ __align__(256) __nv_bfloat16 g_x_hi[M_SZ * E_SZ];
__device__ __align__(256) __nv_bfloat16 g_x_lo[M_SZ * E_SZ];

__device__ __align__(256) __nv_bfloat16 g_q_hi[M_SZ * E_SZ];
__device__ __align__(256) __nv_bfloat16 g_q_lo[M_SZ * E_SZ];
__device__ __align__(256) __nv_bfloat16 g_k_hi[M_SZ * E_SZ];
__device__ __align__(256) __nv_bfloat16 g_k_lo[M_SZ * E_SZ];
__device__ __align__(256) __nv_bfloat16 g_v_hi[M_SZ * E_SZ];
__device__ __align__(256) __nv_bfloat16 g_v_lo[M_SZ * E_SZ];
__device__ __align__(256) __nv_bfloat16 g_ao_hi[M_SZ * E_SZ];
__device__ __align__(256) __nv_bfloat16 g_ao_lo[M_SZ * E_SZ];

__device__ __align__(256) __nv_bfloat16 g_wq_hi[E_SZ * E_SZ];
__device__ __align__(256) __nv_bfloat16 g_wq_lo[E_SZ * E_SZ];
__device__ __align__(256) __nv_bfloat16 g_wk_hi[E_SZ * E_SZ];
__device__ __align__(256) __nv_bfloat16 g_wk_lo[E_SZ * E_SZ];
__device__ __align__(256) __nv_bfloat16 g_wv_hi[E_SZ * E_SZ];
__device__ __align__(256) __nv_bfloat16 g_wv_lo[E_SZ * E_SZ];
__device__ __align__(256) __nv_bfloat16 g_wo_hi[E_SZ * E_SZ];
__device__ __align__(256) __nv_bfloat16 g_wo_lo[E_SZ * E_SZ];

// ================= helpers =================
__device__ __forceinline__ uint32_t smem_u32(const void* p) {
    return (uint32_t)__cvta_generic_to_shared(p);
}

__device__ __forceinline__ void cp_async16(uint32_t dst, const void* src) {
    asm volatile("cp.async.cg.shared.global [%0], [%1], 16;" :: "r"(dst), "l"(src));
}

__device__ __forceinline__ void ldsm_x4(uint32_t addr, uint32_t& r0, uint32_t& r1,
                                        uint32_t& r2, uint32_t& r3) {
    asm volatile("ldmatrix.sync.aligned.m8n8.x4.shared.b16 {%0,%1,%2,%3}, [%4];"
                 : "=r"(r0), "=r"(r1), "=r"(r2), "=r"(r3) : "r"(addr));
}

__device__ __forceinline__ void ldsm_x4_t(uint32_t addr, uint32_t& r0, uint32_t& r1,
                                          uint32_t& r2, uint32_t& r3) {
    asm volatile("ldmatrix.sync.aligned.m8n8.x4.trans.shared.b16 {%0,%1,%2,%3}, [%4];"
                 : "=r"(r0), "=r"(r1), "=r"(r2), "=r"(r3) : "r"(addr));
}

__device__ __forceinline__ void mma_bf16(float* d, const uint32_t* a, const uint32_t* b) {
    asm volatile(
        "mma.sync.aligned.m16n8k16.row.col.f32.bf16.bf16.f32 "
        "{%0,%1,%2,%3}, {%4,%5,%6,%7}, {%8,%9}, {%0,%1,%2,%3};"
        : "+f"(d[0]), "+f"(d[1]), "+f"(d[2]), "+f"(d[3])
        : "r"(a[0]), "r"(a[1]), "r"(a[2]), "r"(a[3]), "r"(b[0]), "r"(b[1]));
}

// swizzle for 64-byte rows (BK=32 bf16)
__device__ __forceinline__ uint32_t swz(int r, int chunk) {
    return (uint32_t)(r * 64 + ((chunk ^ ((r >> 1) & 3)) << 4));
}
// swizzle for 128-byte rows (64 bf16 per row)
__device__ __forceinline__ uint32_t swz128(int r, int chunk) {
    return (uint32_t)(r * 128 + ((chunk ^ (r & 7)) << 4));
}

__device__ __forceinline__ uint32_t pack_bf16(float a, float b) {
    __nv_bfloat162 t = __floats2bfloat162_rn(a, b);
    return *reinterpret_cast<uint32_t*>(&t);
}

// ================= conversion kernels =================
__global__ __launch_bounds__(256) void convert_split(
    const float4* __restrict__ in, __nv_bfloat162* __restrict__ hi,
    __nv_bfloat162* __restrict__ lo, int n4)
{
    int i = blockIdx.x * 256 + threadIdx.x;
    if (i >= n4) return;
    float4 v = in[i];
    __nv_bfloat16 hx = __float2bfloat16(v.x);
    __nv_bfloat16 hy = __float2bfloat16(v.y);
    __nv_bfloat16 hz = __float2bfloat16(v.z);
    __nv_bfloat16 hw = __float2bfloat16(v.w);
    __nv_bfloat16 lx = __float2bfloat16(v.x - __bfloat162float(hx));
    __nv_bfloat16 ly = __float2bfloat16(v.y - __bfloat162float(hy));
    __nv_bfloat16 lz = __float2bfloat16(v.z - __bfloat162float(hz));
    __nv_bfloat16 lw = __float2bfloat16(v.w - __bfloat162float(hw));
    hi[2 * i + 0] = __halves2bfloat162(hx, hy);
    hi[2 * i + 1] = __halves2bfloat162(hz, hw);
    lo[2 * i + 0] = __halves2bfloat162(lx, ly);
    lo[2 * i + 1] = __halves2bfloat162(lz, lw);
}

// W [K,N] fp32 -> Wt [N,K] bf16 hi/lo
__global__ __launch_bounds__(256) void transpose_split(
    const float* __restrict__ W, __nv_bfloat16* __restrict__ Th,
    __nv_bfloat16* __restrict__ Tl)
{
    __shared__ float t[32][33];
    int n0 = blockIdx.x * 32, k0 = blockIdx.y * 32;
    int tx = threadIdx.x & 31;
    int ty = threadIdx.x >> 5;
#pragma unroll
    for (int i = 0; i < 4; i++)
        t[ty + i * 8][tx] = W[(size_t)(k0 + ty + i * 8) * E_SZ + n0 + tx];
    __syncthreads();
#pragma unroll
    for (int i = 0; i < 4; i++) {
        float v = t[tx][ty + i * 8];
        int n = n0 + ty + i * 8, k = k0 + tx;
        __nv_bfloat16 h = __float2bfloat16(v);
        Th[(size_t)n * E_SZ + k] = h;
        Tl[(size_t)n * E_SZ + k] = __float2bfloat16(v - __bfloat162float(h));
    }
}

// ================= HMMA GEMM core =================
#define HT 8192
#define HSTAGE 32768
#define H_SMEM 65536
#define NSTAGES 32   // K=1024 / 32

__device__ __forceinline__ void h_load_tile(uint32_t dst, const __nv_bfloat16* src,
                                            int row0, int k0, int tid) {
#pragma unroll
    for (int i = 0; i < 2; i++) {
        int idx = tid + (i << 8);
        int r = idx >> 2, c = idx & 3;
        cp_async16(dst + swz(r, c),
                   (const void*)(src + (size_t)(row0 + r) * E_SZ + k0 + (c << 3)));
    }
}

// shared mainloop; acc produced in-place
__device__ __forceinline__ void hmma_mainloop(
    uint32_t sb, const __nv_bfloat16* Ah, const __nv_bfloat16* Al,
    const __nv_bfloat16* Bh, const __nv_bfloat16* Bl,
    int m0, int n0, int tid, int wm, int wn, int g, int l8,
    float acc[4][4][4])
{
    h_load_tile(sb + 0 * HT, Ah, m0, 0, tid);
    h_load_tile(sb + 1 * HT, Al, m0, 0, tid);
    h_load_tile(sb + 2 * HT, Bh, n0, 0, tid);
    h_load_tile(sb + 3 * HT, Bl, n0, 0, tid);
    asm volatile("cp.async.commit_group;" ::: "memory");
    h_load_tile(sb + HSTAGE + 0 * HT, Ah, m0, 32, tid);
    h_load_tile(sb + HSTAGE + 1 * HT, Al, m0, 32, tid);
    h_load_tile(sb + HSTAGE + 2 * HT, Bh, n0, 32, tid);
    h_load_tile(sb + HSTAGE + 3 * HT, Bl, n0, 32, tid);
    asm volatile("cp.async.commit_group;" ::: "memory");

    for (int s = 0; s < NSTAGES; s++) {
        if (s + 2 < NSTAGES)
            asm volatile("cp.async.wait_group 1;" ::: "memory");
        else
            asm volatile("cp.async.wait_group 0;" ::: "memory");
        __syncthreads();

        const uint32_t st = sb + (uint32_t)(s & 1) * HSTAGE;
        const uint32_t sAh = st + 0 * HT, sAl = st + 1 * HT;
        const uint32_t sBh = st + 2 * HT, sBl = st + 3 * HT;

#pragma unroll
        for (int k16 = 0; k16 < 2; k16++) {
            const int cb = k16 * 2;
            uint32_t ah[4][4], al[4][4], bh[2][4], bl[2][4];
#pragma unroll
            for (int mt = 0; mt < 4; mt++) {
                int r = wm * 64 + mt * 16 + (g & 1) * 8 + l8;
                int c = cb + (g >> 1);
                ldsm_x4(sAh + swz(r, c), ah[mt][0], ah[mt][1], ah[mt][2], ah[mt][3]);
                ldsm_x4(sAl + swz(r, c), al[mt][0], al[mt][1], al[mt][2], al[mt][3]);
            }
#pragma unroll
            for (int bt = 0; bt < 2; bt++) {
                int r = wn * 32 + bt * 16 + (g >> 1) * 8 + l8;
                int c = cb + (g & 1);
                ldsm_x4(sBh + swz(r, c), bh[bt][0], bh[bt][1], bh[bt][2], bh[bt][3]);
                ldsm_x4(sBl + swz(r, c), bl[bt][0], bl[bt][1], bl[bt][2], bl[bt][3]);
            }
#pragma unroll
            for (int mt = 0; mt < 4; mt++)
#pragma unroll
                for (int nt = 0; nt < 4; nt++) {
                    const int bg = nt >> 1, hs = (nt & 1) * 2;
                    uint32_t bhh[2] = {bh[bg][hs], bh[bg][hs + 1]};
                    uint32_t bll[2] = {bl[bg][hs], bl[bg][hs + 1]};
                    mma_bf16(acc[mt][nt], ah[mt], bhh);
                    mma_bf16(acc[mt][nt], al[mt], bhh);
                    mma_bf16(acc[mt][nt], ah[mt], bll);
                }
        }
        __syncthreads();

        if (s + 2 < NSTAGES) {
            const uint32_t dt = sb + (uint32_t)(s & 1) * HSTAGE;
            const int k0 = (s + 2) * 32;
            h_load_tile(dt + 0 * HT, Ah, m0, k0, tid);
            h_load_tile(dt + 1 * HT, Al, m0, k0, tid);
            h_load_tile(dt + 2 * HT, Bh, n0, k0, tid);
            h_load_tile(dt + 3 * HT, Bl, n0, k0, tid);
            asm volatile("cp.async.commit_group;" ::: "memory");
        }
    }
}

// GEMM with fp32 output (O projection)
__global__ __launch_bounds__(256) void gemm_hmma(
    const __nv_bfloat16* __restrict__ Ah, const __nv_bfloat16* __restrict__ Al,
    const __nv_bfloat16* __restrict__ Bh, const __nv_bfloat16* __restrict__ Bl,
    const float* __restrict__ bias, float* __restrict__ C)
{
    extern __shared__ char smem[];
    const uint32_t sb = smem_u32(smem);
    const int tid = threadIdx.x;
    const int wid = tid >> 5, lane = tid & 31;
    const int wm = wid >> 2, wn = wid & 3;
    const int n0 = blockIdx.x * 128, m0 = blockIdx.y * 128;
    const int g = lane >> 3, l8 = lane & 7;

    float acc[4][4][4];
#pragma unroll
    for (int mt = 0; mt < 4; mt++)
#pragma unroll
        for (int nt = 0; nt < 4; nt++)
#pragma unroll
            for (int r = 0; r < 4; r++) acc[mt][nt][r] = 0.f;

    hmma_mainloop(sb, Ah, Al, Bh, Bl, m0, n0, tid, wm, wn, g, l8, acc);

    const int qr = lane >> 2, qc = (lane & 3) * 2;
#pragma unroll
    for (int mt = 0; mt < 4; mt++)
#pragma unroll
        for (int nt = 0; nt < 4; nt++) {
            int col = n0 + wn * 32 + nt * 8 + qc;
            float2 bv = *(const float2*)(bias + col);
            int row_a = m0 + wm * 64 + mt * 16 + qr;
            float2 o0 = {acc[mt][nt][0] + bv.x, acc[mt][nt][1] + bv.y};
            float2 o1 = {acc[mt][nt][2] + bv.x, acc[mt][nt][3] + bv.y};
            *(float2*)(C + (size_t)row_a * E_SZ + col) = o0;
            *(float2*)(C + (size_t)(row_a + 8) * E_SZ + col) = o1;
        }
}

// GEMM with bf16 hi/lo split output (Q/K/V projections; scale folded for Q)
__global__ __launch_bounds__(256) void gemm_hmma_split(
    const __nv_bfloat16* __restrict__ Ah, const __nv_bfloat16* __restrict__ Al,
    const __nv_bfloat16* __restrict__ Bh, const __nv_bfloat16* __restrict__ Bl,
    const float* __restrict__ bias, float scale,
    __nv_bfloat16* __restrict__ Chi, __nv_bfloat16* __restrict__ Clo)
{
    extern __shared__ char smem[];
    const uint32_t sb = smem_u32(smem);
    const int tid = threadIdx.x;
    const int wid = tid >> 5, lane = tid & 31;
    const int wm = wid >> 2, wn = wid & 3;
    const int n0 = blockIdx.x * 128, m0 = blockIdx.y * 128;
    const int g = lane >> 3, l8 = lane & 7;

    float acc[4][4][4];
#pragma unroll
    for (int mt = 0; mt < 4; mt++)
#pragma unroll
        for (int nt = 0; nt < 4; nt++)
#pragma unroll
            for (int r = 0; r < 4; r++) acc[mt][nt][r] = 0.f;

    hmma_mainloop(sb, Ah, Al, Bh, Bl, m0, n0, tid, wm, wn, g, l8, acc);

    const int qr = lane >> 2, qc = (lane & 3) * 2;
#pragma unroll
    for (int mt = 0; mt < 4; mt++)
#pragma unroll
        for (int nt = 0; nt < 4; nt++) {
            int col = n0 + wn * 32 + nt * 8 + qc;
            float2 bv = *(const float2*)(bias + col);
            int row_a = m0 + wm * 64 + mt * 16 + qr;
#pragma unroll
            for (int half = 0; half < 2; half++) {
                int row = row_a + half * 8;
                float v0 = (acc[mt][nt][half * 2 + 0] + bv.x) * scale;
                float v1 = (acc[mt][nt][half * 2 + 1] + bv.y) * scale;
                __nv_bfloat16 h0 = __float2bfloat16(v0);
                __nv_bfloat16 h1 = __float2bfloat16(v1);
                __nv_bfloat162 hp = __halves2bfloat162(h0, h1);
                __nv_bfloat162 lp = __halves2bfloat162(
                    __float2bfloat16(v0 - __bfloat162float(h0)),
                    __float2bfloat16(v1 - __bfloat162float(h1)));
                *(__nv_bfloat162*)(Chi + (size_t)row * E_SZ + col) = hp;
                *(__nv_bfloat162*)(Clo + (size_t)row * E_SZ + col) = lp;
            }
        }
}

// ================= Flash attention on HMMA (bf16 split, causal) =================
// CTA: 128 q rows x 1 head. 8 warps x 16 rows. Key tiles of 64, double buffered.
// smem: Qhi 16K, Qlo 16K, then 2 stages x (Khi,Klo,Vhi,Vlo each 8K) = 64K. total 96K.
#define FQ 128
#define FK 64
#define FSM_Q 16384
#define FSM_STAGE 32768
#define FSM_TOTAL (2 * FSM_Q + 2 * FSM_STAGE)

__global__ __launch_bounds__(256) void flash_hmma(
    const __nv_bfloat16* __restrict__ Qh, const __nv_bfloat16* __restrict__ Ql,
    const __nv_bfloat16* __restrict__ Kh, const __nv_bfloat16* __restrict__ Kl,
    const __nv_bfloat16* __restrict__ Vh, const __nv_bfloat16* __restrict__ Vl,
    __nv_bfloat16* __restrict__ AOh, __nv_bfloat16* __restrict__ AOl)
{
    extern __shared__ char smem[];
    const uint32_t sb = smem_u32(smem);
    const uint32_t sQh = sb, sQl = sb + FSM_Q;
    const uint32_t sStage = sb + 2 * FSM_Q;

    const int iq = blockIdx.x;          // q tile (0..15)
    const int h  = blockIdx.y;
    const int b  = blockIdx.z;
    const int tid = threadIdx.x;
    const int wid = tid >> 5, lane = tid & 31;
    const int g = lane >> 3, l8 = lane & 7;
    const int qr = lane >> 2, qc = (lane & 3) * 2;

    const int r0 = iq * FQ;
    const int wr = wid * 16;                 // warp's row offset within tile
    const size_t rowbase = (size_t)b * T_SZ; // token row index base
    const int hoff = h * D_SZ;

    // ---- prologue loads: Q tile + key tile 0 ----
    {
        // Q: 128 rows x 8 chunks per array; 1024 chunks / 256 thr = 4 each
#pragma unroll
        for (int i = 0; i < 4; i++) {
            int idx = tid + (i << 8);
            int r = idx >> 3, c = idx & 7;
            const void* srch = (const void*)(Qh + (rowbase + r0 + r) * E_SZ + hoff + (c << 3));
            const void* srcl = (const void*)(Ql + (rowbase + r0 + r) * E_SZ + hoff + (c << 3));
            cp_async16(sQh + swz128(r, c), srch);
            cp_async16(sQl + swz128(r, c), srcl);
        }
        // K/V tile 0: 64 rows x 8 chunks x 4 arrays; 2048/256 = 8 each
#pragma unroll
        for (int i = 0; i < 2; i++) {
            int idx = tid + (i << 8);
            int r = idx >> 3, c = idx & 7;
            size_t go = (rowbase + 0 + r) * E_SZ + hoff + (c << 3);
            cp_async16(sStage + 0     + swz128(r, c), (const void*)(Kh + go));
            cp_async16(sStage + 8192  + swz128(r, c), (const void*)(Kl + go));
            cp_async16(sStage + 16384 + swz128(r, c), (const void*)(Vh + go));
            cp_async16(sStage + 24576 + swz128(r, c), (const void*)(Vl + go));
        }
        asm volatile("cp.async.commit_group;" ::: "memory");
    }

    float oacc[8][4];
#pragma unroll
    for (int nt = 0; nt < 8; nt++)
#pragma unroll
        for (int r = 0; r < 4; r++) oacc[nt][r] = 0.f;
    float m_i[2] = {-INFINITY, -INFINITY};
    float l_i[2] = {0.f, 0.f};

    const int njt = 2 * iq + 2;

    for (int jc = 0; jc < njt; jc++) {
        const int c0 = jc * FK;
        if (jc + 1 < njt) {
            const uint32_t dstS = sStage + (uint32_t)((jc + 1) & 1) * FSM_STAGE;
            const int kr0 = (jc + 1) * FK;
#pragma unroll
            for (int i = 0; i < 2; i++) {
                int idx = tid + (i << 8);
                int r = idx >> 3, c = idx & 7;
                size_t go = (rowbase + kr0 + r) * E_SZ + hoff + (c << 3);
                cp_async16(dstS + 0     + swz128(r, c), (const void*)(Kh + go));
                cp_async16(dstS + 8192  + swz128(r, c), (const void*)(Kl + go));
                cp_async16(dstS + 16384 + swz128(r, c), (const void*)(Vh + go));
                cp_async16(dstS + 24576 + swz128(r, c), (const void*)(Vl + go));
            }
            asm volatile("cp.async.commit_group;" ::: "memory");
            asm volatile("cp.async.wait_group 1;" ::: "memory");
        } else {
            asm volatile("cp.async.wait_group 0;" ::: "memory");
        }
        __syncthreads();

        const bool skip = (c0 > r0 + wr + 15);   // warp fully above diagonal
        if (!skip) {
            const uint32_t st = sStage + (uint32_t)(jc & 1) * FSM_STAGE;
            const uint32_t sKh = st, sKl = st + 8192;
            const uint32_t sVh = st + 16384, sVl = st + 24576;

            // ---- S = Q K^T (3-term split) ----
            float sacc[8][4];
#pragma unroll
            for (int nt = 0; nt < 8; nt++)
#pragma unroll
                for (int r = 0; r < 4; r++) sacc[nt][r] = 0.f;

#pragma unroll
            for (int k16 = 0; k16 < 4; k16++) {
                uint32_t qh[4], ql[4], bh[4][4], bl[4][4];
                {
                    int r = wr + (g & 1) * 8 + l8;
                    int c = k16 * 2 + (g >> 1);
                    ldsm_x4(sQh + swz128(r, c), qh[0], qh[1], qh[2], qh[3]);
                    ldsm_x4(sQl + swz128(r, c), ql[0], ql[1], ql[2], ql[3]);
                }
#pragma unroll
                for (int bt = 0; bt < 4; bt++) {
                    int r = bt * 16 + (g >> 1) * 8 + l8;
                    int c = k16 * 2 + (g & 1);
                    ldsm_x4(sKh + swz128(r, c), bh[bt][0], bh[bt][1], bh[bt][2], bh[bt][3]);
                    ldsm_x4(sKl + swz128(r, c), bl[bt][0], bl[bt][1], bl[bt][2], bl[bt][3]);
                }
#pragma unroll
                for (int nt = 0; nt < 8; nt++) {
                    const int bg = nt >> 1, hs = (nt & 1) * 2;
                    uint32_t bhh[2] = {bh[bg][hs], bh[bg][hs + 1]};
                    uint32_t bll[2] = {bl[bg][hs], bl[bg][hs + 1]};
                    mma_bf16(sacc[nt], qh, bhh);
                    mma_bf16(sacc[nt], ql, bhh);
                    mma_bf16(sacc[nt], qh, bll);
                }
            }

            // ---- causal mask (only when tile touches diagonal for this warp) ----
            if (c0 + FK - 1 > r0 + wr) {
#pragma unroll
                for (int nt = 0; nt < 8; nt++) {
#pragma unroll
                    for (int r = 0; r < 4; r++) {
                        int row = r0 + wr + qr + (r >> 1) * 8;
                        int col = c0 + nt * 8 + qc + (r & 1);
                        if (col > row) sacc[nt][r] = -1e30f;
                    }
                }
            }

            // ---- online softmax ----
            float alpha[2];
#pragma unroll
            for (int i = 0; i < 2; i++) {
                float mx = -INFINITY;
#pragma unroll
                for (int nt = 0; nt < 8; nt++)
                    mx = fmaxf(mx, fmaxf(sacc[nt][2 * i], sacc[nt][2 * i + 1]));
                mx = fmaxf(mx, __shfl_xor_sync(0xffffffffu, mx, 1));
                mx = fmaxf(mx, __shfl_xor_sync(0xffffffffu, mx, 2));
                float mnew = fmaxf(m_i[i], mx);
                alpha[i] = __expf(m_i[i] - mnew);
                float sum = 0.f;
#pragma unroll
                for (int nt = 0; nt < 8; nt++) {
                    float p0 = __expf(sacc[nt][2 * i] - mnew);
                    float p1 = __expf(sacc[nt][2 * i + 1] - mnew);
                    sacc[nt][2 * i] = p0;
                    sacc[nt][2 * i + 1] = p1;
                    sum += p0 + p1;
                }
                sum += __shfl_xor_sync(0xffffffffu, sum, 1);
                sum += __shfl_xor_sync(0xffffffffu, sum, 2);
                l_i[i] = l_i[i] * alpha[i] + sum;
                m_i[i] = mnew;
            }
#pragma unroll
            for (int nt = 0; nt < 8; nt++) {
                oacc[nt][0] *= alpha[0];
                oacc[nt][1] *= alpha[0];
                oacc[nt][2] *= alpha[1];
                oacc[nt][3] *= alpha[1];
            }

            // ---- O += P V (3-term split) ----
#pragma unroll
            for (int k16 = 0; k16 < 4; k16++) {
                // P -> A frags (hi + lo) from sacc tiles 2k16, 2k16+1
                uint32_t phi[4], plo[4];
                {
                    float p00 = sacc[2 * k16][0], p01 = sacc[2 * k16][1];
                    float p10 = sacc[2 * k16][2], p11 = sacc[2 * k16][3];
                    float p20 = sacc[2 * k16 + 1][0], p21 = sacc[2 * k16 + 1][1];
                    float p30 = sacc[2 * k16 + 1][2], p31 = sacc[2 * k16 + 1][3];
                    phi[0] = pack_bf16(p00, p01);
                    phi[1] = pack_bf16(p10, p11);
                    phi[2] = pack_bf16(p20, p21);
                    phi[3] = pack_bf16(p30, p31);
                    __nv_bfloat162* hp;
                    hp = (__nv_bfloat162*)&phi[0];
                    plo[0] = pack_bf16(p00 - __bfloat162float(hp->x), p01 - __bfloat162float(hp->y));
                    hp = (__nv_bfloat162*)&phi[1];
                    plo[1] = pack_bf16(p10 - __bfloat162float(hp->x), p11 - __bfloat162float(hp->y));
                    hp = (__nv_bfloat162*)&phi[2];
                    plo[2] = pack_bf16(p20 - __bfloat162float(hp->x), p21 - __bfloat162float(hp->y));
                    hp = (__nv_bfloat162*)&phi[3];
                    plo[3] = pack_bf16(p30 - __bfloat162float(hp->x), p31 - __bfloat162float(hp->y));
                }
                // V frags (trans): rows = keys, chunks = d
                uint32_t vh[4][4], vl[4][4];
#pragma unroll
                for (int bt = 0; bt < 4; bt++) {
                    int r = k16 * 16 + (g & 1) * 8 + l8;
                    int c = bt * 2 + (g >> 1);
                    ldsm_x4_t(sVh + swz128(r, c), vh[bt][0], vh[bt][1], vh[bt][2], vh[bt][3]);
                    ldsm_x4_t(sVl + swz128(r, c), vl[bt][0], vl[bt][1], vl[bt][2], vl[bt][3]);
                }
#pragma unroll
                for (int nt = 0; nt < 8; nt++) {
                    const int bg = nt >> 1, hs = (nt & 1) * 2;
                    uint32_t bvh[2] = {vh[bg][hs], vh[bg][hs + 1]};
                    uint32_t bvl[2] = {vl[bg][hs], vl[bg][hs + 1]};
                    mma_bf16(oacc[nt], phi, bvh);
                    mma_bf16(oacc[nt], plo, bvh);
                    mma_bf16(oacc[nt], phi, bvl);
                }
            }
        }
        __syncthreads();
    }

    // ---- epilogue: normalize + split-write bf16 hi/lo ----
    float inv0 = 1.f / l_i[0];
    float inv1 = 1.f / l_i[1];
#pragma unroll
    for (int nt = 0; nt < 8; nt++) {
#pragma unroll
        for (int halfr = 0; halfr < 2; halfr++) {
            float inv = halfr ? inv1 : inv0;
            float v0 = oacc[nt][halfr * 2 + 0] * inv;
            float v1 = oacc[nt][halfr * 2 + 1] * inv;
            int row = r0 + wr + qr + halfr * 8;
            int d = nt * 8 + qc;
            __nv_bfloat16 h0 = __float2bfloat16(v0);
            __nv_bfloat16 h1 = __float2bfloat16(v1);
            __nv_bfloat162 hp = __halves2bfloat162(h0, h1);
            __nv_bfloat162 lp = __halves2bfloat162(
                __float2bfloat16(v0 - __bfloat162float(h0)),
                __float2bfloat16(v1 - __bfloat162float(h1)));
            size_t off = (rowbase + row) * E_SZ + hoff + d;
            *(__nv_bfloat162*)(AOh + off) = hp;
            *(__nv_bfloat162*)(AOl + off) = lp;
        }
    }
}

// ======================= launch =======================
extern "C" void kernel_launch(void* const* d_in, const int* in_sizes, int n_in,
                              void* d_out, int out_size)
{
    const float* x  = (const float*)d_in[0];
    const float* Wq = (const float*)d_in[1];
    const float* bq = (const float*)d_in[2];
    const float* Wk = (const float*)d_in[3];
    const float* bk = (const float*)d_in[4];
    const float* Wv = (const float*)d_in[5];
    const float* bv = (const float*)d_in[6];
    const float* Wo = (const float*)d_in[7];
    const float* bo = (const float*)d_in[8];
    float* out = (float*)d_out;

    __nv_bfloat16 *xh, *xl;
    cudaGetSymbolAddress((void**)&xh, g_x_hi);
    cudaGetSymbolAddress((void**)&xl, g_x_lo);
    __nv_bfloat16 *qh, *ql, *kh, *kl, *vh, *vl, *aoh, *aol;
    cudaGetSymbolAddress((void**)&qh,  g_q_hi);
    cudaGetSymbolAddress((void**)&ql,  g_q_lo);
    cudaGetSymbolAddress((void**)&kh,  g_k_hi);
    cudaGetSymbolAddress((void**)&kl,  g_k_lo);
    cudaGetSymbolAddress((void**)&vh,  g_v_hi);
    cudaGetSymbolAddress((void**)&vl,  g_v_lo);
    cudaGetSymbolAddress((void**)&aoh, g_ao_hi);
    cudaGetSymbolAddress((void**)&aol, g_ao_lo);

    __nv_bfloat16 *wqh, *wql, *wkh, *wkl, *wvh, *wvl, *woh, *wol;
    cudaGetSymbolAddress((void**)&wqh, g_wq_hi);
    cudaGetSymbolAddress((void**)&wql, g_wq_lo);
    cudaGetSymbolAddress((void**)&wkh, g_wk_hi);
    cudaGetSymbolAddress((void**)&wkl, g_wk_lo);
    cudaGetSymbolAddress((void**)&wvh, g_wv_hi);
    cudaGetSymbolAddress((void**)&wvl, g_wv_lo);
    cudaGetSymbolAddress((void**)&woh, g_wo_hi);
    cudaGetSymbolAddress((void**)&wol, g_wo_lo);

    cudaFuncSetAttribute(gemm_hmma, cudaFuncAttributeMaxDynamicSharedMemorySize, H_SMEM);
    cudaFuncSetAttribute(gemm_hmma_split, cudaFuncAttributeMaxDynamicSharedMemorySize, H_SMEM);
    cudaFuncSetAttribute(flash_hmma, cudaFuncAttributeMaxDynamicSharedMemorySize, FSM_TOTAL);

    const int n4 = (M_SZ * E_SZ) / 4;

    // 1) split x
    convert_split<<<(n4 + 255) / 256, 256>>>((const float4*)x,
        (__nv_bfloat162*)xh, (__nv_bfloat162*)xl, n4);

    // 2) transpose+split weights
    dim3 tgrid(E_SZ / 32, E_SZ / 32);
    transpose_split<<<tgrid, 256>>>(Wq, wqh, wql);
    transpose_split<<<tgrid, 256>>>(Wk, wkh, wkl);
    transpose_split<<<tgrid, 256>>>(Wv, wvh, wvl);
    transpose_split<<<tgrid, 256>>>(Wo, woh, wol);

    // 3) Q/K/V projections -> bf16 hi/lo (scale folded into Q)
    dim3 ggrid(E_SZ / 128, M_SZ / 128);
    gemm_hmma_split<<<ggrid, 256, H_SMEM>>>(xh, xl, wqh, wql, bq, 0.03125f, qh, ql);
    gemm_hmma_split<<<ggrid, 256, H_SMEM>>>(xh, xl, wkh, wkl, bk, 1.0f, kh, kl);
    gemm_hmma_split<<<ggrid, 256, H_SMEM>>>(xh, xl, wvh, wvl, bv, 1.0f, vh, vl);

    // 4) attention (HMMA) -> ao hi/lo
    flash_hmma<<<dim3(T_SZ / FQ, H_SZ, B_SZ), 256, FSM_TOTAL>>>(
        qh, ql, kh, kl, vh, vl, aoh, aol);

    // 5) O projection -> fp32 out
    gemm_hmma<<<ggrid, 256, H_SMEM>>>(aoh, aol, woh, wol, bo, out);
}